// round 13
// baseline (speedup 1.0000x reference)
#include <cuda_runtime.h>
#include <cuda_bf16.h>
#include <stdint.h>

// Problem constants
#define BB 128
#define TT 256
#define CC 512
#define HH 2048
#define NCTA 256          /* persistent grid: 2 CTAs per SM */
#define NBLK 64           /* weight N-block count (32-col blocks of H) */

__device__ __constant__ float k_DT      = (float)(1.0/765.0);
__device__ __constant__ float k_HALF_DT = (float)(0.5/765.0);
__device__ __constant__ float k_SIXTH   = (float)(1.0/(765.0*6.0));

// ---------------- device-global scratch ----------------
// Weights pre-packed in mma.m16n8k16 B-fragment register order (see prep_kernel).
__device__ __align__(16) uint32_t g_W1p[NBLK * 8192];    // 64 blks x (512*32/2)
__device__ __align__(16) uint32_t g_W2p[NBLK * 32768];   // 64 blks x (2048*32/2)
__device__ __align__(16) uint32_t g_W3p[32 * 16384];     // 32 grps x (2048*16/2)

__device__ __align__(16) __nv_bfloat16 g_a [BB*CC];      // bf16 MLP input
__device__ __align__(16) __nv_bfloat16 g_h1[BB*HH];
__device__ __align__(16) __nv_bfloat16 g_h2[BB*HH];
__device__ float g_y[BB*CC];                             // fp32 initial state (read once)

// ---------------- leaderless grid barrier (monotone counter) ----------------
__device__ unsigned g_count;

__device__ __forceinline__ void grid_barrier(unsigned &target){
    __syncthreads();
    if (threadIdx.x == 0){
        __threadfence();                         // release prior writes
        atomicAdd(&g_count, 1u);
        while (*((volatile unsigned*)&g_count) < target) { }
        __threadfence();                         // acquire
    }
    __syncthreads();
    target += gridDim.x;
}

// ---------------- PTX helpers ----------------
__device__ __forceinline__ void cp16(void* s, const void* g){
    uint32_t sa = (uint32_t)__cvta_generic_to_shared(s);
    asm volatile("cp.async.cg.shared.global [%0], [%1], 16;\n" :: "r"(sa), "l"(g));
}
__device__ __forceinline__ void cpcommit(){ asm volatile("cp.async.commit_group;\n"); }
template<int N> __device__ __forceinline__ void cpwait(){
    asm volatile("cp.async.wait_group %0;\n" :: "n"(N));
}
__device__ __forceinline__ void cpwait_dyn(int allow){
    if (allow >= 2)      cpwait<2>();
    else if (allow == 1) cpwait<1>();
    else                 cpwait<0>();
}

__device__ __forceinline__ void mma16816(float* c, const uint32_t* a, const uint32_t* b){
    asm volatile(
        "mma.sync.aligned.m16n8k16.row.col.f32.bf16.bf16.f32 "
        "{%0,%1,%2,%3},{%4,%5,%6,%7},{%8,%9},{%0,%1,%2,%3};\n"
        : "+f"(c[0]), "+f"(c[1]), "+f"(c[2]), "+f"(c[3])
        : "r"(a[0]), "r"(a[1]), "r"(a[2]), "r"(a[3]), "r"(b[0]), "r"(b[1]));
}

__device__ __forceinline__ void ldsm4(uint32_t* a, const __nv_bfloat16* p){
    uint32_t addr = (uint32_t)__cvta_generic_to_shared(p);
    asm volatile("ldmatrix.sync.aligned.m8n8.x4.shared.b16 {%0,%1,%2,%3},[%4];\n"
        : "=r"(a[0]), "=r"(a[1]), "=r"(a[2]), "=r"(a[3]) : "r"(addr));
}

__device__ __forceinline__ uint32_t packbf(__nv_bfloat16 lo, __nv_bfloat16 hi){
    union { __nv_bfloat162 v; uint32_t u; } t;
    t.v.x = lo; t.v.y = hi; return t.u;
}
__device__ __forceinline__ float fast_tanh(float x){
    float y; asm("tanh.approx.f32 %0, %1;" : "=f"(y) : "f"(x)); return y;
}

// ---------------- smem layout (dynamic, 104448 B per CTA; 2 CTAs/SM) --------
// L1/L2 view: As12 4 stages x [32][136] bf16 = 34816 B at 0
//             Bs12 4 stages x 2048 u32       = 32768 B at 34816   (ends 67584)
// L3 view:    As3  3 stages x [4q][16][136]  = 52224 B at 0
//             Bs3  3 stages x 4096 u32       = 49152 B at 52224   (ends 101376)
//             Red  768 floats                =  3072 B at 101376
#define SMEM_BYTES 104448
#define ASTG12 4352          /* bf16 per L1/L2 A stage */
#define BSTG12 2048          /* u32 per L1/L2 B stage  */
#define ASTG3  8704          /* bf16 per L3 A stage    */
#define BSTG3  4096          /* u32 per L3 B stage     */

// ---------------- layer 1/2 load helpers (KC=128) ----------------
template<int KDIM>
__device__ __forceinline__ void l12_loadA(const __nv_bfloat16* __restrict__ Ag,
                                          __nv_bfloat16* __restrict__ As,
                                          int c, int st, int tid){
    __nv_bfloat16* dst = As + st * ASTG12;
    const __nv_bfloat16* src = Ag + c * 128;
    #pragma unroll
    for (int i=0;i<2;i++){                      // 512 x 16B tasks (32 rows x 16 segs)
        int task = i*256 + tid;
        int row = task >> 4, seg = task & 15;
        cp16(dst + row*136 + seg*8, src + row*KDIM + seg*8);
    }
}
__device__ __forceinline__ void l12_loadB(const uint32_t* __restrict__ Bg,
                                          uint32_t* __restrict__ Bs,
                                          int c, int st, int tid){
    #pragma unroll
    for (int i=0;i<2;i++){                      // 512 x 16B tasks
        int task = i*256 + tid;
        cp16(Bs + st*BSTG12 + task*4, Bg + c*BSTG12 + task*4);
    }
}
// prefetch B stages 0,1 (issued BEFORE the grid barrier; two commit groups)
__device__ __forceinline__ void l12_prefB(const uint32_t* __restrict__ Bg,
                                          uint32_t* __restrict__ Bs, int tid){
    l12_loadB(Bg, Bs, 0, 0, tid); cpcommit();
    l12_loadB(Bg, Bs, 1, 1, tid); cpcommit();
}

// ---------------- layers 1 & 2: D = tanh(A @ W + b) -> bf16 ----------------
// Tile 32x32, warps 2(M)x4(N), KC=128, 4 stages, prefetch distance 3.
// Commit-group order: [B0][B1] (pre-barrier) [A0][A1][A2,B2] then [Ac,Bc].
// Chunk c ready <=> groups 0..c+2 complete  =>  allow = min(2, NC-1-c).
template<int KDIM>
__device__ __forceinline__ void layer12(
    const __nv_bfloat16* __restrict__ Ag,
    const uint32_t* __restrict__ Bg,
    __nv_bfloat16* __restrict__ As,
    uint32_t* __restrict__ Bs,
    __nv_bfloat16* __restrict__ Og,
    const float br[2],
    int tid, int lane, int wm, int wn, int g8, int t4, int mb, int nb)
{
    constexpr int NC = KDIM / 128;
    float acc[4] = {0.f, 0.f, 0.f, 0.f};

    l12_loadA<KDIM>(Ag, As, 0, 0, tid); cpcommit();
    l12_loadA<KDIM>(Ag, As, 1, 1, tid); cpcommit();
    l12_loadA<KDIM>(Ag, As, 2, 2, tid);
    l12_loadB(Bg, Bs, 2, 2, tid); cpcommit();

    for (int c=0; c<NC; c++){
        cpwait_dyn(min(2, NC-1-c));
        __syncthreads();
        { int cn = c + 3;
          if (cn < NC){
              l12_loadA<KDIM>(Ag, As, cn, cn & 3, tid);
              l12_loadB(Bg, Bs, cn, cn & 3, tid);
              cpcommit();
          } }

        const __nv_bfloat16* Ast = As + (c & 3) * ASTG12;
        const uint32_t*      Bst = Bs + (c & 3) * BSTG12;
        #pragma unroll
        for (int ks=0; ks<8; ks++){
            uint32_t a[4];
            ldsm4(a, Ast + (wm*16 + (lane&15))*136 + ks*16 + (lane>>4)*8);
            uint2 bp = *reinterpret_cast<const uint2*>(
                Bst + ((ks*4 + wn)*32 + lane)*2);
            mma16816(acc, a, reinterpret_cast<const uint32_t*>(&bp));
        }
    }

    int r0 = mb + wm*16 + g8;
    int gc = nb + wn*8 + t4*2;
    union { __nv_bfloat162 v2; uint32_t u; } x0, x1;
    x0.v2.x = __float2bfloat16(fast_tanh(acc[0] + br[0]));
    x0.v2.y = __float2bfloat16(fast_tanh(acc[1] + br[1]));
    x1.v2.x = __float2bfloat16(fast_tanh(acc[2] + br[0]));
    x1.v2.y = __float2bfloat16(fast_tanh(acc[3] + br[1]));
    *reinterpret_cast<uint32_t*>(&Og[r0 * HH + gc])       = x0.u;
    *reinterpret_cast<uint32_t*>(&Og[(r0 + 8) * HH + gc]) = x1.u;
}

// ---------------- layer 3 load helpers ----------------
__device__ __forceinline__ void l3_loadA(const __nv_bfloat16* __restrict__ Ag,
                                         __nv_bfloat16* __restrict__ As,
                                         int c, int st, int tid){
    __nv_bfloat16* dst = As + st * ASTG3;
    #pragma unroll
    for (int i=0;i<4;i++){                      // 1024 tasks: 4q x 16 rows x 16 segs
        int task = i*256 + tid;
        int q = task >> 8, rem = task & 255;
        int row = rem >> 4, seg = rem & 15;
        cp16(dst + q*2176 + row*136 + seg*8,
             Ag + row*HH + q*512 + c*128 + seg*8);
    }
}
__device__ __forceinline__ void l3_loadB(const uint32_t* __restrict__ Bg,
                                         uint32_t* __restrict__ Bs,
                                         int c, int st, int tid){
    #pragma unroll
    for (int i=0;i<4;i++){                      // 1024 tasks: 4q x 1024 u32
        int task = i*256 + tid;
        int q = task >> 8, j = task & 255;
        cp16(Bs + st*BSTG3 + q*1024 + j*4, Bg + q*4096 + c*1024 + j*4);
    }
}
__device__ __forceinline__ void l3_prefB(const uint32_t* __restrict__ Bg,
                                         uint32_t* __restrict__ Bs, int tid){
    l3_loadB(Bg, Bs, 0, 0, tid); cpcommit();
    l3_loadB(Bg, Bs, 1, 1, tid); cpcommit();
}

// ---------------- layer 3: k = h2 @ W3 + b3, fused RK4 (register state) ----
// Tile 16x16, warps 2(N)x4(K-quarter), NC=4 chunks, 3 stages, distance 2.
// RK4 state (y, ksum) lives in wk==0 warp registers across the whole kernel.
__device__ __forceinline__ void layer3(
    const __nv_bfloat16* __restrict__ Ag,
    const uint32_t* __restrict__ Bg,
    __nv_bfloat16* __restrict__ As,
    uint32_t* __restrict__ Bs,
    float* __restrict__ Red,
    const float b3r[2],
    float yreg[4], float ksreg[4],
    int s, int out_t, float* __restrict__ out,
    int tid, int lane, int wn3, int wk, int g8, int t4, int mb3, int nb3)
{
    constexpr int NC = 4;
    float acc[4] = {0.f, 0.f, 0.f, 0.f};

    l3_loadA(Ag, As, 0, 0, tid); cpcommit();
    l3_loadA(Ag, As, 1, 1, tid); cpcommit();

    for (int c=0; c<NC; c++){
        cpwait_dyn(min(1, NC-1-c));
        __syncthreads();
        { int cn = c + 2;
          if (cn < NC){
              l3_loadA(Ag, As, cn, cn % 3, tid);
              l3_loadB(Bg, Bs, cn, cn % 3, tid);
              cpcommit();
          } }

        const __nv_bfloat16* Ast = As + (c % 3) * ASTG3 + wk*2176;
        const uint32_t*      Bst = Bs + (c % 3) * BSTG3 + wk*1024;
        #pragma unroll
        for (int ks=0; ks<8; ks++){
            uint32_t a[4];
            ldsm4(a, Ast + (lane&15)*136 + ks*16 + (lane>>4)*8);
            uint2 bp = *reinterpret_cast<const uint2*>(
                Bst + ((ks*2 + wn3)*32 + lane)*2);
            mma16816(acc, a, reinterpret_cast<const uint32_t*>(&bp));
        }
    }

    // 4-way split-K reduction: wk=1..3 publish, wk=0 adds + RK4 epilogue
    if (wk > 0){
        float* slot = Red + ((wk-1)*2 + wn3)*128 + lane*4;
        slot[0] = acc[0]; slot[1] = acc[1]; slot[2] = acc[2]; slot[3] = acc[3];
    }
    __syncthreads();
    if (wk == 0){
        #pragma unroll
        for (int j=0;j<3;j++){
            const float* slot = Red + (j*2 + wn3)*128 + lane*4;
            acc[0] += slot[0]; acc[1] += slot[1];
            acc[2] += slot[2]; acc[3] += slot[3];
        }
        float kv[4];
        kv[0] = acc[0] + b3r[0]; kv[1] = acc[1] + b3r[1];
        kv[2] = acc[2] + b3r[0]; kv[3] = acc[3] + b3r[1];

        int r0 = mb3 + g8;
        int gc = nb3 + wn3*8 + t4*2;
        uint32_t apack[2];
        if (s == 3){
            #pragma unroll
            for (int q=0;q<4;q++){
                float total = ksreg[q] + kv[q];
                yreg[q] = fmaf(k_SIXTH, total, yreg[q]);
            }
            apack[0] = packbf(__float2bfloat16(yreg[0]), __float2bfloat16(yreg[1]));
            apack[1] = packbf(__float2bfloat16(yreg[2]), __float2bfloat16(yreg[3]));
            if (out_t >= 0){
                float* o0 = &out[r0 * TT * CC + out_t * CC + gc];
                float* o1 = &out[(r0 + 8) * TT * CC + out_t * CC + gc];
                o0[0] = yreg[0]; o0[1] = yreg[1];
                o1[0] = yreg[2]; o1[1] = yreg[3];
            }
        } else {
            float al = (s == 2) ? k_DT : k_HALF_DT;
            #pragma unroll
            for (int q=0;q<4;q++)
                ksreg[q] = (s == 0) ? kv[q] : fmaf(2.f, kv[q], ksreg[q]);
            apack[0] = packbf(__float2bfloat16(fmaf(al, kv[0], yreg[0])),
                              __float2bfloat16(fmaf(al, kv[1], yreg[1])));
            apack[1] = packbf(__float2bfloat16(fmaf(al, kv[2], yreg[2])),
                              __float2bfloat16(fmaf(al, kv[3], yreg[3])));
        }
        *reinterpret_cast<uint32_t*>(&g_a[r0 * CC + gc])       = apack[0];
        *reinterpret_cast<uint32_t*>(&g_a[(r0 + 8) * CC + gc]) = apack[1];
    }
}

// ---------------- persistent kernel ----------------
__global__ void __launch_bounds__(256, 2)
ode_kernel(const float* __restrict__ b1,
           const float* __restrict__ b2,
           const float* __restrict__ b3,
           float* __restrict__ out)
{
    extern __shared__ __align__(16) char smem[];
    __nv_bfloat16* As12 = reinterpret_cast<__nv_bfloat16*>(smem);
    uint32_t*      Bs12 = reinterpret_cast<uint32_t*>(smem + 34816);
    __nv_bfloat16* As3  = reinterpret_cast<__nv_bfloat16*>(smem);
    uint32_t*      Bs3  = reinterpret_cast<uint32_t*>(smem + 52224);
    float*         Red  = reinterpret_cast<float*>(smem + 101376);

    const int tid  = threadIdx.x;
    const int lane = tid & 31;
    const int warp = tid >> 5;
    const int wm   = warp & 1;            // L1/L2: M warp (2)
    const int wn   = warp >> 1;           // L1/L2: N warp (4)
    const int wn3  = warp & 1;            // L3: N warp (2)
    const int wk   = warp >> 1;           // L3: K-quarter warp (4)
    const int g8   = lane >> 2;
    const int t4   = lane & 3;
    const int cta  = blockIdx.x;
    const int mb   = (cta >> 6) * 32;     // L1/L2 row base (4 quarters)
    const int nb   = (cta & 63) * 32;     // L1/L2 column base
    const int mb3  = (cta >> 5) * 16;     // L3 row base (8 tiles)
    const int nb3  = (cta & 31) * 16;     // L3 column base

    float b1r[2], b2r[2], b3r[2];
    { int c = nb + wn*8 + t4*2;  b1r[0] = b1[c]; b1r[1] = b1[c+1];
                                 b2r[0] = b2[c]; b2r[1] = b2[c+1]; }
    { int c = nb3 + wn3*8 + t4*2; b3r[0] = b3[c]; b3r[1] = b3[c+1]; }

    // RK4 state registers (wk==0 warps own 4 elements each, fixed forever)
    float yreg[4] = {0.f,0.f,0.f,0.f}, ksreg[4] = {0.f,0.f,0.f,0.f};
    if (wk == 0){
        int r0 = mb3 + g8;
        int gc = nb3 + wn3*8 + t4*2;
        yreg[0] = g_y[r0 * CC + gc];       yreg[1] = g_y[r0 * CC + gc + 1];
        yreg[2] = g_y[(r0 + 8) * CC + gc]; yreg[3] = g_y[(r0 + 8) * CC + gc + 1];
    }

    const uint32_t* W1g = g_W1p + (cta & 63) * 8192;
    const uint32_t* W2g = g_W2p + (cta & 63) * 32768;
    const uint32_t* W3g = g_W3p + (cta & 31) * 16384;
    unsigned target = gridDim.x;

    for (int t = 1; t < TT; t++){
        for (int sub = 0; sub < 3; sub++){
            for (int s = 0; s < 4; s++){
                __syncthreads();                 // Bs12 free of prior readers
                l12_prefB(W1g, Bs12, tid);       // B indep. of barrier
                grid_barrier(target);
                layer12<CC>(g_a + mb*CC, W1g, As12, Bs12, g_h1, b1r,
                            tid, lane, wm, wn, g8, t4, mb, nb);

                __syncthreads();
                l12_prefB(W2g, Bs12, tid);
                grid_barrier(target);
                layer12<HH>(g_h1 + mb*HH, W2g, As12, Bs12, g_h2, b2r,
                            tid, lane, wm, wn, g8, t4, mb, nb);

                __syncthreads();
                l3_prefB(W3g, Bs3, tid);
                grid_barrier(target);
                const int out_t = (s == 3 && sub == 2) ? t : -1;
                layer3(g_h2 + mb3*HH, W3g, As3, Bs3, Red, b3r,
                       yreg, ksreg, s, out_t, out,
                       tid, lane, wn3, wk, g8, t4, mb3, nb3);
            }
        }
    }
}

// ---------------- prep: pack weights to fragment order, init state ----------------
__global__ void prep_kernel(const float* __restrict__ x,
                            const float* __restrict__ W1,
                            const float* __restrict__ W2,
                            const float* __restrict__ W3,
                            float* __restrict__ out)
{
    int i = blockIdx.x * blockDim.x + threadIdx.x;
    if (i == 0){ g_count = 0; }

    if (i < NBLK * 32768){                 // W2 pack
        int blk = i >> 15, q = i & 32767;
        int reg = q & 1, lane = (q >> 1) & 31, u = q >> 6;
        int g = u & 3, tt = u >> 2;
        int n = blk*32 + g*8 + (lane >> 2);
        int k = tt*16 + (lane & 3)*2 + reg*8;
        g_W2p[i] = packbf(__float2bfloat16(W2[k*HH + n]),
                          __float2bfloat16(W2[(k+1)*HH + n]));
    }
    if (i < NBLK * 8192){                  // W1 pack
        int blk = i >> 13, q = i & 8191;
        int reg = q & 1, lane = (q >> 1) & 31, u = q >> 6;
        int g = u & 3, tt = u >> 2;
        int n = blk*32 + g*8 + (lane >> 2);
        int k = tt*16 + (lane & 3)*2 + reg*8;
        g_W1p[i] = packbf(__float2bfloat16(W1[k*HH + n]),
                          __float2bfloat16(W1[(k+1)*HH + n]));
    }
    if (i < 32 * 16384){                   // W3 pack
        int grp = i >> 14, q = i & 16383;
        int reg = q & 1, lane = (q >> 1) & 31, u = q >> 6;
        int wn = u & 1, tt = u >> 1;
        int n = grp*16 + wn*8 + (lane >> 2);
        int k = tt*16 + (lane & 3)*2 + reg*8;
        g_W3p[i] = packbf(__float2bfloat16(W3[k*CC + n]),
                          __float2bfloat16(W3[(k+1)*CC + n]));
    }
    if (i < BB * CC){                      // state init
        int b = i >> 9, c = i & (CC - 1);
        float v = x[b * TT * CC + c];
        g_y[i] = v;
        g_a[i] = __float2bfloat16(v);
        out[b * TT * CC + c] = v;
    }
}

// ---------------- launcher: 2 graph nodes ----------------
extern "C" void kernel_launch(void* const* d_in, const int* in_sizes, int n_in,
                              void* d_out, int out_size)
{
    const float* x  = (const float*)d_in[0];
    const float* W1 = (const float*)d_in[1];
    const float* b1 = (const float*)d_in[2];
    const float* W2 = (const float*)d_in[3];
    const float* b2 = (const float*)d_in[4];
    const float* W3 = (const float*)d_in[5];
    const float* b3 = (const float*)d_in[6];
    float* out = (float*)d_out;

    (void)in_sizes; (void)n_in; (void)out_size;

    cudaFuncSetAttribute(ode_kernel, cudaFuncAttributeMaxDynamicSharedMemorySize,
                         SMEM_BYTES);

    prep_kernel<<<(NBLK * 32768 + 255) / 256, 256>>>(x, W1, W2, W3, out);
    ode_kernel<<<NCTA, 256, SMEM_BYTES>>>(b1, b2, b3, out);
}

// round 14
// speedup vs baseline: 1.0049x; 1.0049x over previous
#include <cuda_runtime.h>
#include <cuda_bf16.h>
#include <stdint.h>

// Problem constants
#define BB 128
#define TT 256
#define CC 512
#define HH 2048
#define NCTA 256          /* persistent grid: 2 CTAs per SM */
#define NBLK 64           /* weight N-block count (32-col blocks of H) */

__device__ __constant__ float k_DT      = (float)(1.0/765.0);
__device__ __constant__ float k_HALF_DT = (float)(0.5/765.0);
__device__ __constant__ float k_SIXTH   = (float)(1.0/(765.0*6.0));

// ---------------- device-global scratch ----------------
// Weights pre-packed in mma.m16n8k16 B-fragment register order (see prep_kernel).
__device__ __align__(16) uint32_t g_W1p[NBLK * 8192];    // 64 blks x (512*32/2)
__device__ __align__(16) uint32_t g_W2p[NBLK * 32768];   // 64 blks x (2048*32/2)
__device__ __align__(16) uint32_t g_W3p[32 * 16384];     // 32 grps x (2048*16/2)

__device__ __align__(16) __nv_bfloat16 g_a [BB*CC];      // bf16 MLP input
__device__ __align__(16) __nv_bfloat16 g_h1[BB*HH];
__device__ __align__(16) __nv_bfloat16 g_h2[BB*HH];
__device__ float g_y[BB*CC];                             // fp32 initial state (read once)

// ---------------- leaderless grid barrier (monotone counter) ----------------
__device__ unsigned g_count;

__device__ __forceinline__ void grid_barrier(unsigned &target){
    __syncthreads();
    if (threadIdx.x == 0){
        __threadfence();                         // release prior writes
        atomicAdd(&g_count, 1u);
        while (*((volatile unsigned*)&g_count) < target) { }
        __threadfence();                         // acquire
    }
    __syncthreads();
    target += gridDim.x;
}

// ---------------- PTX helpers ----------------
__device__ __forceinline__ void cp16(void* s, const void* g){
    uint32_t sa = (uint32_t)__cvta_generic_to_shared(s);
    asm volatile("cp.async.cg.shared.global [%0], [%1], 16;\n" :: "r"(sa), "l"(g));
}
__device__ __forceinline__ void cpcommit(){ asm volatile("cp.async.commit_group;\n"); }
template<int N> __device__ __forceinline__ void cpwait(){
    asm volatile("cp.async.wait_group %0;\n" :: "n"(N));
}
__device__ __forceinline__ void cpwait_dyn(int allow){
    if (allow >= 4)      cpwait<4>();
    else if (allow == 3) cpwait<3>();
    else if (allow == 2) cpwait<2>();
    else if (allow == 1) cpwait<1>();
    else                 cpwait<0>();
}

__device__ __forceinline__ void mma16816(float* c, const uint32_t* a, const uint32_t* b){
    asm volatile(
        "mma.sync.aligned.m16n8k16.row.col.f32.bf16.bf16.f32 "
        "{%0,%1,%2,%3},{%4,%5,%6,%7},{%8,%9},{%0,%1,%2,%3};\n"
        : "+f"(c[0]), "+f"(c[1]), "+f"(c[2]), "+f"(c[3])
        : "r"(a[0]), "r"(a[1]), "r"(a[2]), "r"(a[3]), "r"(b[0]), "r"(b[1]));
}

__device__ __forceinline__ void ldsm4(uint32_t* a, const __nv_bfloat16* p){
    uint32_t addr = (uint32_t)__cvta_generic_to_shared(p);
    asm volatile("ldmatrix.sync.aligned.m8n8.x4.shared.b16 {%0,%1,%2,%3},[%4];\n"
        : "=r"(a[0]), "=r"(a[1]), "=r"(a[2]), "=r"(a[3]) : "r"(addr));
}

__device__ __forceinline__ uint32_t packbf(__nv_bfloat16 lo, __nv_bfloat16 hi){
    union { __nv_bfloat162 v; uint32_t u; } t;
    t.v.x = lo; t.v.y = hi; return t.u;
}
__device__ __forceinline__ float fast_tanh(float x){
    float y; asm("tanh.approx.f32 %0, %1;" : "=f"(y) : "f"(x)); return y;
}

// ---------------- smem layout (dynamic, 104448 B per CTA; 2 CTAs/SM) --------
// L1/L2 view: As12 6 stages x [32][136] bf16 = 52224 B at 0
//             Bs12 6 stages x 2048 u32       = 49152 B at 52224   (ends 101376)
// L3 view:    As3  3 stages x [4q][16][136]  = 52224 B at 0
//             Bs3  3 stages x 4096 u32       = 49152 B at 52224   (ends 101376)
//             Red  768 floats                =  3072 B at 101376
#define SMEM_BYTES 104448
#define ASTG12 4352          /* bf16 per L1/L2 A stage */
#define BSTG12 2048          /* u32 per L1/L2 B stage  */
#define ASTG3  8704          /* bf16 per L3 A stage    */
#define BSTG3  4096          /* u32 per L3 B stage     */

// ---------------- layer 1/2 load helpers (KC=128) ----------------
template<int KDIM>
__device__ __forceinline__ void l12_loadA(const __nv_bfloat16* __restrict__ Ag,
                                          __nv_bfloat16* __restrict__ As,
                                          int c, int st, int tid){
    __nv_bfloat16* dst = As + st * ASTG12;
    const __nv_bfloat16* src = Ag + c * 128;
    #pragma unroll
    for (int i=0;i<2;i++){                      // 512 x 16B tasks (32 rows x 16 segs)
        int task = i*256 + tid;
        int row = task >> 4, seg = task & 15;
        cp16(dst + row*136 + seg*8, src + row*KDIM + seg*8);
    }
}
__device__ __forceinline__ void l12_loadB(const uint32_t* __restrict__ Bg,
                                          uint32_t* __restrict__ Bs,
                                          int c, int st, int tid){
    #pragma unroll
    for (int i=0;i<2;i++){                      // 512 x 16B tasks
        int task = i*256 + tid;
        cp16(Bs + st*BSTG12 + task*4, Bg + c*BSTG12 + task*4);
    }
}
// prefetch B stages 0,1 (issued BEFORE the grid barrier; two commit groups)
__device__ __forceinline__ void l12_prefB(const uint32_t* __restrict__ Bg,
                                          uint32_t* __restrict__ Bs, int tid){
    l12_loadB(Bg, Bs, 0, 0, tid); cpcommit();
    l12_loadB(Bg, Bs, 1, 1, tid); cpcommit();
}

// ---------------- layers 1 & 2: D = tanh(A @ W + b) -> bf16 ----------------
// Tile 32x32, warps 2(M)x4(N), KC=128, 6 stages, prefetch distance 5.
// Group order: [B0][B1] (pre-barrier) [A0][A1][A2B2][A3B3][A4B4], then per
// chunk c (post-wait) [Ac+5,Bc+5]. Chunk c needs groups <= c+2 complete
//   =>  allow = min(4, NC-1-c)   (verified for NC=4 and NC=16, incl. tails).
template<int KDIM>
__device__ __forceinline__ void layer12(
    const __nv_bfloat16* __restrict__ Ag,
    const uint32_t* __restrict__ Bg,
    __nv_bfloat16* __restrict__ As,
    uint32_t* __restrict__ Bs,
    __nv_bfloat16* __restrict__ Og,
    const float br[2],
    int tid, int lane, int wm, int wn, int g8, int t4, int mb, int nb)
{
    constexpr int NC = KDIM / 128;
    float acc[4] = {0.f, 0.f, 0.f, 0.f};

    l12_loadA<KDIM>(Ag, As, 0, 0, tid); cpcommit();
    l12_loadA<KDIM>(Ag, As, 1, 1, tid); cpcommit();
    #pragma unroll
    for (int d=2; d<5; d++){
        if (d < NC){
            l12_loadA<KDIM>(Ag, As, d, d, tid);
            l12_loadB(Bg, Bs, d, d, tid);
            cpcommit();
        }
    }

    for (int c=0; c<NC; c++){
        cpwait_dyn(min(4, NC-1-c));
        __syncthreads();
        { int cn = c + 5;
          if (cn < NC){
              int st = cn % 6;
              l12_loadA<KDIM>(Ag, As, cn, st, tid);
              l12_loadB(Bg, Bs, cn, st, tid);
              cpcommit();
          } }

        const int stc = c % 6;
        const __nv_bfloat16* Ast = As + stc * ASTG12;
        const uint32_t*      Bst = Bs + stc * BSTG12;
        #pragma unroll
        for (int ks=0; ks<8; ks++){
            uint32_t a[4];
            ldsm4(a, Ast + (wm*16 + (lane&15))*136 + ks*16 + (lane>>4)*8);
            uint2 bp = *reinterpret_cast<const uint2*>(
                Bst + ((ks*4 + wn)*32 + lane)*2);
            mma16816(acc, a, reinterpret_cast<const uint32_t*>(&bp));
        }
    }

    int r0 = mb + wm*16 + g8;
    int gc = nb + wn*8 + t4*2;
    union { __nv_bfloat162 v2; uint32_t u; } x0, x1;
    x0.v2.x = __float2bfloat16(fast_tanh(acc[0] + br[0]));
    x0.v2.y = __float2bfloat16(fast_tanh(acc[1] + br[1]));
    x1.v2.x = __float2bfloat16(fast_tanh(acc[2] + br[0]));
    x1.v2.y = __float2bfloat16(fast_tanh(acc[3] + br[1]));
    *reinterpret_cast<uint32_t*>(&Og[r0 * HH + gc])       = x0.u;
    *reinterpret_cast<uint32_t*>(&Og[(r0 + 8) * HH + gc]) = x1.u;
}

// ---------------- layer 3 load helpers ----------------
__device__ __forceinline__ void l3_loadA(const __nv_bfloat16* __restrict__ Ag,
                                         __nv_bfloat16* __restrict__ As,
                                         int c, int st, int tid){
    __nv_bfloat16* dst = As + st * ASTG3;
    #pragma unroll
    for (int i=0;i<4;i++){                      // 1024 tasks: 4q x 16 rows x 16 segs
        int task = i*256 + tid;
        int q = task >> 8, rem = task & 255;
        int row = rem >> 4, seg = rem & 15;
        cp16(dst + q*2176 + row*136 + seg*8,
             Ag + row*HH + q*512 + c*128 + seg*8);
    }
}
__device__ __forceinline__ void l3_loadB(const uint32_t* __restrict__ Bg,
                                         uint32_t* __restrict__ Bs,
                                         int c, int st, int tid){
    #pragma unroll
    for (int i=0;i<4;i++){                      // 1024 tasks: 4q x 1024 u32
        int task = i*256 + tid;
        int q = task >> 8, j = task & 255;
        cp16(Bs + st*BSTG3 + q*1024 + j*4, Bg + q*4096 + c*1024 + j*4);
    }
}
__device__ __forceinline__ void l3_prefB(const uint32_t* __restrict__ Bg,
                                         uint32_t* __restrict__ Bs, int tid){
    l3_loadB(Bg, Bs, 0, 0, tid); cpcommit();
    l3_loadB(Bg, Bs, 1, 1, tid); cpcommit();
}

// ---------------- layer 3: k = h2 @ W3 + b3, fused RK4 (register state) ----
// Tile 16x16, warps 2(N)x4(K-quarter), NC=4 chunks, 3 stages, distance 2.
// RK4 state (y, ksum) lives in wk==0 warp registers across the whole kernel.
__device__ __forceinline__ void layer3(
    const __nv_bfloat16* __restrict__ Ag,
    const uint32_t* __restrict__ Bg,
    __nv_bfloat16* __restrict__ As,
    uint32_t* __restrict__ Bs,
    float* __restrict__ Red,
    const float b3r[2],
    float yreg[4], float ksreg[4],
    int s, int out_t, float* __restrict__ out,
    int tid, int lane, int wn3, int wk, int g8, int t4, int mb3, int nb3)
{
    constexpr int NC = 4;
    float acc[4] = {0.f, 0.f, 0.f, 0.f};

    l3_loadA(Ag, As, 0, 0, tid); cpcommit();
    l3_loadA(Ag, As, 1, 1, tid); cpcommit();

    for (int c=0; c<NC; c++){
        cpwait_dyn(min(1, NC-1-c));
        __syncthreads();
        { int cn = c + 2;
          if (cn < NC){
              l3_loadA(Ag, As, cn, cn % 3, tid);
              l3_loadB(Bg, Bs, cn, cn % 3, tid);
              cpcommit();
          } }

        const __nv_bfloat16* Ast = As + (c % 3) * ASTG3 + wk*2176;
        const uint32_t*      Bst = Bs + (c % 3) * BSTG3 + wk*1024;
        #pragma unroll
        for (int ks=0; ks<8; ks++){
            uint32_t a[4];
            ldsm4(a, Ast + (lane&15)*136 + ks*16 + (lane>>4)*8);
            uint2 bp = *reinterpret_cast<const uint2*>(
                Bst + ((ks*2 + wn3)*32 + lane)*2);
            mma16816(acc, a, reinterpret_cast<const uint32_t*>(&bp));
        }
    }

    // 4-way split-K reduction: wk=1..3 publish, wk=0 adds + RK4 epilogue
    if (wk > 0){
        float* slot = Red + ((wk-1)*2 + wn3)*128 + lane*4;
        slot[0] = acc[0]; slot[1] = acc[1]; slot[2] = acc[2]; slot[3] = acc[3];
    }
    __syncthreads();
    if (wk == 0){
        #pragma unroll
        for (int j=0;j<3;j++){
            const float* slot = Red + (j*2 + wn3)*128 + lane*4;
            acc[0] += slot[0]; acc[1] += slot[1];
            acc[2] += slot[2]; acc[3] += slot[3];
        }
        float kv[4];
        kv[0] = acc[0] + b3r[0]; kv[1] = acc[1] + b3r[1];
        kv[2] = acc[2] + b3r[0]; kv[3] = acc[3] + b3r[1];

        int r0 = mb3 + g8;
        int gc = nb3 + wn3*8 + t4*2;
        uint32_t apack[2];
        if (s == 3){
            #pragma unroll
            for (int q=0;q<4;q++){
                float total = ksreg[q] + kv[q];
                yreg[q] = fmaf(k_SIXTH, total, yreg[q]);
            }
            apack[0] = packbf(__float2bfloat16(yreg[0]), __float2bfloat16(yreg[1]));
            apack[1] = packbf(__float2bfloat16(yreg[2]), __float2bfloat16(yreg[3]));
            if (out_t >= 0){
                float* o0 = &out[r0 * TT * CC + out_t * CC + gc];
                float* o1 = &out[(r0 + 8) * TT * CC + out_t * CC + gc];
                o0[0] = yreg[0]; o0[1] = yreg[1];
                o1[0] = yreg[2]; o1[1] = yreg[3];
            }
        } else {
            float al = (s == 2) ? k_DT : k_HALF_DT;
            #pragma unroll
            for (int q=0;q<4;q++)
                ksreg[q] = (s == 0) ? kv[q] : fmaf(2.f, kv[q], ksreg[q]);
            apack[0] = packbf(__float2bfloat16(fmaf(al, kv[0], yreg[0])),
                              __float2bfloat16(fmaf(al, kv[1], yreg[1])));
            apack[1] = packbf(__float2bfloat16(fmaf(al, kv[2], yreg[2])),
                              __float2bfloat16(fmaf(al, kv[3], yreg[3])));
        }
        *reinterpret_cast<uint32_t*>(&g_a[r0 * CC + gc])       = apack[0];
        *reinterpret_cast<uint32_t*>(&g_a[(r0 + 8) * CC + gc]) = apack[1];
    }
}

// ---------------- persistent kernel ----------------
__global__ void __launch_bounds__(256, 2)
ode_kernel(const float* __restrict__ b1,
           const float* __restrict__ b2,
           const float* __restrict__ b3,
           float* __restrict__ out)
{
    extern __shared__ __align__(16) char smem[];
    __nv_bfloat16* As12 = reinterpret_cast<__nv_bfloat16*>(smem);
    uint32_t*      Bs12 = reinterpret_cast<uint32_t*>(smem + 52224);
    __nv_bfloat16* As3  = reinterpret_cast<__nv_bfloat16*>(smem);
    uint32_t*      Bs3  = reinterpret_cast<uint32_t*>(smem + 52224);
    float*         Red  = reinterpret_cast<float*>(smem + 101376);

    const int tid  = threadIdx.x;
    const int lane = tid & 31;
    const int warp = tid >> 5;
    const int wm   = warp & 1;            // L1/L2: M warp (2)
    const int wn   = warp >> 1;           // L1/L2: N warp (4)
    const int wn3  = warp & 1;            // L3: N warp (2)
    const int wk   = warp >> 1;           // L3: K-quarter warp (4)
    const int g8   = lane >> 2;
    const int t4   = lane & 3;
    const int cta  = blockIdx.x;
    const int mb   = (cta >> 6) * 32;     // L1/L2 row base (4 quarters)
    const int nb   = (cta & 63) * 32;     // L1/L2 column base
    const int mb3  = (cta >> 5) * 16;     // L3 row base (8 tiles)
    const int nb3  = (cta & 31) * 16;     // L3 column base

    float b1r[2], b2r[2], b3r[2];
    { int c = nb + wn*8 + t4*2;  b1r[0] = b1[c]; b1r[1] = b1[c+1];
                                 b2r[0] = b2[c]; b2r[1] = b2[c+1]; }
    { int c = nb3 + wn3*8 + t4*2; b3r[0] = b3[c]; b3r[1] = b3[c+1]; }

    // RK4 state registers (wk==0 warps own 4 elements each, fixed forever)
    float yreg[4] = {0.f,0.f,0.f,0.f}, ksreg[4] = {0.f,0.f,0.f,0.f};
    if (wk == 0){
        int r0 = mb3 + g8;
        int gc = nb3 + wn3*8 + t4*2;
        yreg[0] = g_y[r0 * CC + gc];       yreg[1] = g_y[r0 * CC + gc + 1];
        yreg[2] = g_y[(r0 + 8) * CC + gc]; yreg[3] = g_y[(r0 + 8) * CC + gc + 1];
    }

    const uint32_t* W1g = g_W1p + (cta & 63) * 8192;
    const uint32_t* W2g = g_W2p + (cta & 63) * 32768;
    const uint32_t* W3g = g_W3p + (cta & 31) * 16384;
    unsigned target = gridDim.x;

    for (int t = 1; t < TT; t++){
        for (int sub = 0; sub < 3; sub++){
            for (int s = 0; s < 4; s++){
                __syncthreads();                 // Bs12 free of prior readers
                l12_prefB(W1g, Bs12, tid);       // B indep. of barrier
                grid_barrier(target);
                layer12<CC>(g_a + mb*CC, W1g, As12, Bs12, g_h1, b1r,
                            tid, lane, wm, wn, g8, t4, mb, nb);

                __syncthreads();
                l12_prefB(W2g, Bs12, tid);
                grid_barrier(target);
                layer12<HH>(g_h1 + mb*HH, W2g, As12, Bs12, g_h2, b2r,
                            tid, lane, wm, wn, g8, t4, mb, nb);

                __syncthreads();
                l3_prefB(W3g, Bs3, tid);
                grid_barrier(target);
                const int out_t = (s == 3 && sub == 2) ? t : -1;
                layer3(g_h2 + mb3*HH, W3g, As3, Bs3, Red, b3r,
                       yreg, ksreg, s, out_t, out,
                       tid, lane, wn3, wk, g8, t4, mb3, nb3);
            }
        }
    }
}

// ---------------- prep: pack weights to fragment order, init state ----------------
__global__ void prep_kernel(const float* __restrict__ x,
                            const float* __restrict__ W1,
                            const float* __restrict__ W2,
                            const float* __restrict__ W3,
                            float* __restrict__ out)
{
    int i = blockIdx.x * blockDim.x + threadIdx.x;
    if (i == 0){ g_count = 0; }

    if (i < NBLK * 32768){                 // W2 pack
        int blk = i >> 15, q = i & 32767;
        int reg = q & 1, lane = (q >> 1) & 31, u = q >> 6;
        int g = u & 3, tt = u >> 2;
        int n = blk*32 + g*8 + (lane >> 2);
        int k = tt*16 + (lane & 3)*2 + reg*8;
        g_W2p[i] = packbf(__float2bfloat16(W2[k*HH + n]),
                          __float2bfloat16(W2[(k+1)*HH + n]));
    }
    if (i < NBLK * 8192){                  // W1 pack
        int blk = i >> 13, q = i & 8191;
        int reg = q & 1, lane = (q >> 1) & 31, u = q >> 6;
        int g = u & 3, tt = u >> 2;
        int n = blk*32 + g*8 + (lane >> 2);
        int k = tt*16 + (lane & 3)*2 + reg*8;
        g_W1p[i] = packbf(__float2bfloat16(W1[k*HH + n]),
                          __float2bfloat16(W1[(k+1)*HH + n]));
    }
    if (i < 32 * 16384){                   // W3 pack
        int grp = i >> 14, q = i & 16383;
        int reg = q & 1, lane = (q >> 1) & 31, u = q >> 6;
        int wn = u & 1, tt = u >> 1;
        int n = grp*16 + wn*8 + (lane >> 2);
        int k = tt*16 + (lane & 3)*2 + reg*8;
        g_W3p[i] = packbf(__float2bfloat16(W3[k*CC + n]),
                          __float2bfloat16(W3[(k+1)*CC + n]));
    }
    if (i < BB * CC){                      // state init
        int b = i >> 9, c = i & (CC - 1);
        float v = x[b * TT * CC + c];
        g_y[i] = v;
        g_a[i] = __float2bfloat16(v);
        out[b * TT * CC + c] = v;
    }
}

// ---------------- launcher: 2 graph nodes ----------------
extern "C" void kernel_launch(void* const* d_in, const int* in_sizes, int n_in,
                              void* d_out, int out_size)
{
    const float* x  = (const float*)d_in[0];
    const float* W1 = (const float*)d_in[1];
    const float* b1 = (const float*)d_in[2];
    const float* W2 = (const float*)d_in[3];
    const float* b2 = (const float*)d_in[4];
    const float* W3 = (const float*)d_in[5];
    const float* b3 = (const float*)d_in[6];
    float* out = (float*)d_out;

    (void)in_sizes; (void)n_in; (void)out_size;

    cudaFuncSetAttribute(ode_kernel, cudaFuncAttributeMaxDynamicSharedMemorySize,
                         SMEM_BYTES);

    prep_kernel<<<(NBLK * 32768 + 255) / 256, 256>>>(x, W1, W2, W3, out);
    ode_kernel<<<NCTA, 256, SMEM_BYTES>>>(b1, b2, b3, out);
}

// round 15
// speedup vs baseline: 1.0520x; 1.0468x over previous
#include <cuda_runtime.h>
#include <cuda_bf16.h>
#include <stdint.h>

// Problem constants
#define BB 128
#define TT 256
#define CC 512
#define HH 2048
#define NCTA 256          /* persistent grid: 2 CTAs per SM */
#define NBLK 64           /* weight N-block count (32-col blocks of H) */

__device__ __constant__ float k_DT      = (float)(1.0/765.0);
__device__ __constant__ float k_HALF_DT = (float)(0.5/765.0);
__device__ __constant__ float k_SIXTH   = (float)(1.0/(765.0*6.0));

// ---------------- device-global scratch ----------------
// Weights pre-packed in mma.m16n8k16 B-fragment register order (see prep_kernel).
__device__ __align__(16) uint32_t g_W1p[NBLK * 8192];    // 64 blks x (512*32/2)
__device__ __align__(16) uint32_t g_W2p[NBLK * 32768];   // 64 blks x (2048*32/2)
__device__ __align__(16) uint32_t g_W3p[32 * 16384];     // 32 grps x (2048*16/2)

__device__ __align__(16) __nv_bfloat16 g_a [BB*CC];      // bf16 MLP input
__device__ __align__(16) __nv_bfloat16 g_h1[BB*HH];
__device__ __align__(16) __nv_bfloat16 g_h2[BB*HH];
__device__ float g_y[BB*CC];                             // fp32 initial state (read once)

// ---------------- per-quarter leaderless barriers ----------------
// The three layers partition batch rows identically: each row-quarter
// q = cta>>6 (rows [32q, 32q+32)) is a CLOSED pipeline — all activations a
// quarter's CTAs read are produced by the same quarter's 64 CTAs. So each
// barrier only needs to span 64 CTAs. 4 counters on separate 128B lines.
__device__ unsigned g_cnt[4 * 32];

__device__ __forceinline__ void quarter_barrier(unsigned &target, int q){
    __syncthreads();
    if (threadIdx.x == 0){
        volatile unsigned* cnt = &g_cnt[q * 32];
        __threadfence();                         // release prior writes
        atomicAdd((unsigned*)cnt, 1u);
        while (*cnt < target) { }
        __threadfence();                         // acquire
    }
    __syncthreads();
    target += 64u;
}

// ---------------- PTX helpers ----------------
__device__ __forceinline__ void cp16(void* s, const void* g){
    uint32_t sa = (uint32_t)__cvta_generic_to_shared(s);
    asm volatile("cp.async.cg.shared.global [%0], [%1], 16;\n" :: "r"(sa), "l"(g));
}
__device__ __forceinline__ void cpcommit(){ asm volatile("cp.async.commit_group;\n"); }
template<int N> __device__ __forceinline__ void cpwait(){
    asm volatile("cp.async.wait_group %0;\n" :: "n"(N));
}
__device__ __forceinline__ void cpwait_dyn(int allow){
    if (allow >= 4)      cpwait<4>();
    else if (allow == 3) cpwait<3>();
    else if (allow == 2) cpwait<2>();
    else if (allow == 1) cpwait<1>();
    else                 cpwait<0>();
}

__device__ __forceinline__ void mma16816(float* c, const uint32_t* a, const uint32_t* b){
    asm volatile(
        "mma.sync.aligned.m16n8k16.row.col.f32.bf16.bf16.f32 "
        "{%0,%1,%2,%3},{%4,%5,%6,%7},{%8,%9},{%0,%1,%2,%3};\n"
        : "+f"(c[0]), "+f"(c[1]), "+f"(c[2]), "+f"(c[3])
        : "r"(a[0]), "r"(a[1]), "r"(a[2]), "r"(a[3]), "r"(b[0]), "r"(b[1]));
}

__device__ __forceinline__ void ldsm4(uint32_t* a, const __nv_bfloat16* p){
    uint32_t addr = (uint32_t)__cvta_generic_to_shared(p);
    asm volatile("ldmatrix.sync.aligned.m8n8.x4.shared.b16 {%0,%1,%2,%3},[%4];\n"
        : "=r"(a[0]), "=r"(a[1]), "=r"(a[2]), "=r"(a[3]) : "r"(addr));
}

__device__ __forceinline__ uint32_t packbf(__nv_bfloat16 lo, __nv_bfloat16 hi){
    union { __nv_bfloat162 v; uint32_t u; } t;
    t.v.x = lo; t.v.y = hi; return t.u;
}
__device__ __forceinline__ float fast_tanh(float x){
    float y; asm("tanh.approx.f32 %0, %1;" : "=f"(y) : "f"(x)); return y;
}

// ---------------- smem layout (dynamic, 104448 B per CTA; 2 CTAs/SM) --------
// L1/L2 view: As12 6 stages x [32][136] bf16 = 52224 B at 0
//             Bs12 6 stages x 2048 u32       = 49152 B at 52224   (ends 101376)
// L3 view:    As3  3 stages x [4q][16][136]  = 52224 B at 0
//             Bs3  3 stages x 4096 u32       = 49152 B at 52224   (ends 101376)
//             Red  768 floats                =  3072 B at 101376
#define SMEM_BYTES 104448
#define ASTG12 4352          /* bf16 per L1/L2 A stage */
#define BSTG12 2048          /* u32 per L1/L2 B stage  */
#define ASTG3  8704          /* bf16 per L3 A stage    */
#define BSTG3  4096          /* u32 per L3 B stage     */

// ---------------- layer 1/2 load helpers (KC=128) ----------------
template<int KDIM>
__device__ __forceinline__ void l12_loadA(const __nv_bfloat16* __restrict__ Ag,
                                          __nv_bfloat16* __restrict__ As,
                                          int c, int st, int tid){
    __nv_bfloat16* dst = As + st * ASTG12;
    const __nv_bfloat16* src = Ag + c * 128;
    #pragma unroll
    for (int i=0;i<2;i++){                      // 512 x 16B tasks (32 rows x 16 segs)
        int task = i*256 + tid;
        int row = task >> 4, seg = task & 15;
        cp16(dst + row*136 + seg*8, src + row*KDIM + seg*8);
    }
}
__device__ __forceinline__ void l12_loadB(const uint32_t* __restrict__ Bg,
                                          uint32_t* __restrict__ Bs,
                                          int c, int st, int tid){
    #pragma unroll
    for (int i=0;i<2;i++){                      // 512 x 16B tasks
        int task = i*256 + tid;
        cp16(Bs + st*BSTG12 + task*4, Bg + c*BSTG12 + task*4);
    }
}
// prefetch B stages 0,1 (issued BEFORE the quarter barrier; two commit groups)
__device__ __forceinline__ void l12_prefB(const uint32_t* __restrict__ Bg,
                                          uint32_t* __restrict__ Bs, int tid){
    l12_loadB(Bg, Bs, 0, 0, tid); cpcommit();
    l12_loadB(Bg, Bs, 1, 1, tid); cpcommit();
}

// ---------------- layers 1 & 2: D = tanh(A @ W + b) -> bf16 ----------------
// Tile 32x32, warps 2(M)x4(N), KC=128, 6 stages, prefetch distance 5.
// Group order: [B0][B1] (pre-barrier) [A0][A1][A2B2][A3B3][A4B4], then per
// chunk c (post-wait) [Ac+5,Bc+5]. Chunk c needs groups <= c+2 complete
//   =>  allow = min(4, NC-1-c).
template<int KDIM>
__device__ __forceinline__ void layer12(
    const __nv_bfloat16* __restrict__ Ag,
    const uint32_t* __restrict__ Bg,
    __nv_bfloat16* __restrict__ As,
    uint32_t* __restrict__ Bs,
    __nv_bfloat16* __restrict__ Og,
    const float br[2],
    int tid, int lane, int wm, int wn, int g8, int t4, int mb, int nb)
{
    constexpr int NC = KDIM / 128;
    float acc[4] = {0.f, 0.f, 0.f, 0.f};

    l12_loadA<KDIM>(Ag, As, 0, 0, tid); cpcommit();
    l12_loadA<KDIM>(Ag, As, 1, 1, tid); cpcommit();
    #pragma unroll
    for (int d=2; d<5; d++){
        if (d < NC){
            l12_loadA<KDIM>(Ag, As, d, d, tid);
            l12_loadB(Bg, Bs, d, d, tid);
            cpcommit();
        }
    }

    for (int c=0; c<NC; c++){
        cpwait_dyn(min(4, NC-1-c));
        __syncthreads();
        { int cn = c + 5;
          if (cn < NC){
              int st = cn % 6;
              l12_loadA<KDIM>(Ag, As, cn, st, tid);
              l12_loadB(Bg, Bs, cn, st, tid);
              cpcommit();
          } }

        const int stc = c % 6;
        const __nv_bfloat16* Ast = As + stc * ASTG12;
        const uint32_t*      Bst = Bs + stc * BSTG12;
        #pragma unroll
        for (int ks=0; ks<8; ks++){
            uint32_t a[4];
            ldsm4(a, Ast + (wm*16 + (lane&15))*136 + ks*16 + (lane>>4)*8);
            uint2 bp = *reinterpret_cast<const uint2*>(
                Bst + ((ks*4 + wn)*32 + lane)*2);
            mma16816(acc, a, reinterpret_cast<const uint32_t*>(&bp));
        }
    }

    int r0 = mb + wm*16 + g8;
    int gc = nb + wn*8 + t4*2;
    union { __nv_bfloat162 v2; uint32_t u; } x0, x1;
    x0.v2.x = __float2bfloat16(fast_tanh(acc[0] + br[0]));
    x0.v2.y = __float2bfloat16(fast_tanh(acc[1] + br[1]));
    x1.v2.x = __float2bfloat16(fast_tanh(acc[2] + br[0]));
    x1.v2.y = __float2bfloat16(fast_tanh(acc[3] + br[1]));
    *reinterpret_cast<uint32_t*>(&Og[r0 * HH + gc])       = x0.u;
    *reinterpret_cast<uint32_t*>(&Og[(r0 + 8) * HH + gc]) = x1.u;
}

// ---------------- layer 3 load helpers ----------------
__device__ __forceinline__ void l3_loadA(const __nv_bfloat16* __restrict__ Ag,
                                         __nv_bfloat16* __restrict__ As,
                                         int c, int st, int tid){
    __nv_bfloat16* dst = As + st * ASTG3;
    #pragma unroll
    for (int i=0;i<4;i++){                      // 1024 tasks: 4q x 16 rows x 16 segs
        int task = i*256 + tid;
        int q = task >> 8, rem = task & 255;
        int row = rem >> 4, seg = rem & 15;
        cp16(dst + q*2176 + row*136 + seg*8,
             Ag + row*HH + q*512 + c*128 + seg*8);
    }
}
__device__ __forceinline__ void l3_loadB(const uint32_t* __restrict__ Bg,
                                         uint32_t* __restrict__ Bs,
                                         int c, int st, int tid){
    #pragma unroll
    for (int i=0;i<4;i++){                      // 1024 tasks: 4q x 1024 u32
        int task = i*256 + tid;
        int q = task >> 8, j = task & 255;
        cp16(Bs + st*BSTG3 + q*1024 + j*4, Bg + q*4096 + c*1024 + j*4);
    }
}
__device__ __forceinline__ void l3_prefB(const uint32_t* __restrict__ Bg,
                                         uint32_t* __restrict__ Bs, int tid){
    l3_loadB(Bg, Bs, 0, 0, tid); cpcommit();
    l3_loadB(Bg, Bs, 1, 1, tid); cpcommit();
}

// ---------------- layer 3: k = h2 @ W3 + b3, fused RK4 (register state) ----
// Tile 16x16, warps 2(N)x4(K-quarter), NC=4 chunks, 3 stages, distance 2.
// RK4 state (y, ksum) lives in wk==0 warp registers across the whole kernel.
__device__ __forceinline__ void layer3(
    const __nv_bfloat16* __restrict__ Ag,
    const uint32_t* __restrict__ Bg,
    __nv_bfloat16* __restrict__ As,
    uint32_t* __restrict__ Bs,
    float* __restrict__ Red,
    const float b3r[2],
    float yreg[4], float ksreg[4],
    int s, int out_t, float* __restrict__ out,
    int tid, int lane, int wn3, int wk, int g8, int t4, int mb3, int nb3)
{
    constexpr int NC = 4;
    float acc[4] = {0.f, 0.f, 0.f, 0.f};

    l3_loadA(Ag, As, 0, 0, tid); cpcommit();
    l3_loadA(Ag, As, 1, 1, tid); cpcommit();

    for (int c=0; c<NC; c++){
        cpwait_dyn(min(1, NC-1-c));
        __syncthreads();
        { int cn = c + 2;
          if (cn < NC){
              l3_loadA(Ag, As, cn, cn % 3, tid);
              l3_loadB(Bg, Bs, cn, cn % 3, tid);
              cpcommit();
          } }

        const __nv_bfloat16* Ast = As + (c % 3) * ASTG3 + wk*2176;
        const uint32_t*      Bst = Bs + (c % 3) * BSTG3 + wk*1024;
        #pragma unroll
        for (int ks=0; ks<8; ks++){
            uint32_t a[4];
            ldsm4(a, Ast + (lane&15)*136 + ks*16 + (lane>>4)*8);
            uint2 bp = *reinterpret_cast<const uint2*>(
                Bst + ((ks*2 + wn3)*32 + lane)*2);
            mma16816(acc, a, reinterpret_cast<const uint32_t*>(&bp));
        }
    }

    // 4-way split-K reduction: wk=1..3 publish, wk=0 adds + RK4 epilogue
    if (wk > 0){
        float* slot = Red + ((wk-1)*2 + wn3)*128 + lane*4;
        slot[0] = acc[0]; slot[1] = acc[1]; slot[2] = acc[2]; slot[3] = acc[3];
    }
    __syncthreads();
    if (wk == 0){
        #pragma unroll
        for (int j=0;j<3;j++){
            const float* slot = Red + (j*2 + wn3)*128 + lane*4;
            acc[0] += slot[0]; acc[1] += slot[1];
            acc[2] += slot[2]; acc[3] += slot[3];
        }
        float kv[4];
        kv[0] = acc[0] + b3r[0]; kv[1] = acc[1] + b3r[1];
        kv[2] = acc[2] + b3r[0]; kv[3] = acc[3] + b3r[1];

        int r0 = mb3 + g8;
        int gc = nb3 + wn3*8 + t4*2;
        uint32_t apack[2];
        if (s == 3){
            #pragma unroll
            for (int q=0;q<4;q++){
                float total = ksreg[q] + kv[q];
                yreg[q] = fmaf(k_SIXTH, total, yreg[q]);
            }
            apack[0] = packbf(__float2bfloat16(yreg[0]), __float2bfloat16(yreg[1]));
            apack[1] = packbf(__float2bfloat16(yreg[2]), __float2bfloat16(yreg[3]));
            if (out_t >= 0){
                float* o0 = &out[r0 * TT * CC + out_t * CC + gc];
                float* o1 = &out[(r0 + 8) * TT * CC + out_t * CC + gc];
                o0[0] = yreg[0]; o0[1] = yreg[1];
                o1[0] = yreg[2]; o1[1] = yreg[3];
            }
        } else {
            float al = (s == 2) ? k_DT : k_HALF_DT;
            #pragma unroll
            for (int q=0;q<4;q++)
                ksreg[q] = (s == 0) ? kv[q] : fmaf(2.f, kv[q], ksreg[q]);
            apack[0] = packbf(__float2bfloat16(fmaf(al, kv[0], yreg[0])),
                              __float2bfloat16(fmaf(al, kv[1], yreg[1])));
            apack[1] = packbf(__float2bfloat16(fmaf(al, kv[2], yreg[2])),
                              __float2bfloat16(fmaf(al, kv[3], yreg[3])));
        }
        *reinterpret_cast<uint32_t*>(&g_a[r0 * CC + gc])       = apack[0];
        *reinterpret_cast<uint32_t*>(&g_a[(r0 + 8) * CC + gc]) = apack[1];
    }
}

// ---------------- persistent kernel ----------------
__global__ void __launch_bounds__(256, 2)
ode_kernel(const float* __restrict__ b1,
           const float* __restrict__ b2,
           const float* __restrict__ b3,
           float* __restrict__ out)
{
    extern __shared__ __align__(16) char smem[];
    __nv_bfloat16* As12 = reinterpret_cast<__nv_bfloat16*>(smem);
    uint32_t*      Bs12 = reinterpret_cast<uint32_t*>(smem + 52224);
    __nv_bfloat16* As3  = reinterpret_cast<__nv_bfloat16*>(smem);
    uint32_t*      Bs3  = reinterpret_cast<uint32_t*>(smem + 52224);
    float*         Red  = reinterpret_cast<float*>(smem + 101376);

    const int tid  = threadIdx.x;
    const int lane = tid & 31;
    const int warp = tid >> 5;
    const int wm   = warp & 1;            // L1/L2: M warp (2)
    const int wn   = warp >> 1;           // L1/L2: N warp (4)
    const int wn3  = warp & 1;            // L3: N warp (2)
    const int wk   = warp >> 1;           // L3: K-quarter warp (4)
    const int g8   = lane >> 2;
    const int t4   = lane & 3;
    const int cta  = blockIdx.x;
    const int qid  = cta >> 6;            // row-quarter: the closed pipeline id
    const int mb   = qid * 32;            // L1/L2 row base
    const int nb   = (cta & 63) * 32;     // L1/L2 column base
    const int mb3  = (cta >> 5) * 16;     // L3 row base (within same quarter)
    const int nb3  = (cta & 31) * 16;     // L3 column base

    float b1r[2], b2r[2], b3r[2];
    { int c = nb + wn*8 + t4*2;  b1r[0] = b1[c]; b1r[1] = b1[c+1];
                                 b2r[0] = b2[c]; b2r[1] = b2[c+1]; }
    { int c = nb3 + wn3*8 + t4*2; b3r[0] = b3[c]; b3r[1] = b3[c+1]; }

    // RK4 state registers (wk==0 warps own 4 elements each, fixed forever)
    float yreg[4] = {0.f,0.f,0.f,0.f}, ksreg[4] = {0.f,0.f,0.f,0.f};
    if (wk == 0){
        int r0 = mb3 + g8;
        int gc = nb3 + wn3*8 + t4*2;
        yreg[0] = g_y[r0 * CC + gc];       yreg[1] = g_y[r0 * CC + gc + 1];
        yreg[2] = g_y[(r0 + 8) * CC + gc]; yreg[3] = g_y[(r0 + 8) * CC + gc + 1];
    }

    const uint32_t* W1g = g_W1p + (cta & 63) * 8192;
    const uint32_t* W2g = g_W2p + (cta & 63) * 32768;
    const uint32_t* W3g = g_W3p + (cta & 31) * 16384;
    unsigned target = 64u;

    for (int t = 1; t < TT; t++){
        for (int sub = 0; sub < 3; sub++){
            for (int s = 0; s < 4; s++){
                __syncthreads();                 // Bs12 free of prior readers
                l12_prefB(W1g, Bs12, tid);       // B indep. of barrier
                quarter_barrier(target, qid);
                layer12<CC>(g_a + mb*CC, W1g, As12, Bs12, g_h1, b1r,
                            tid, lane, wm, wn, g8, t4, mb, nb);

                __syncthreads();
                l12_prefB(W2g, Bs12, tid);
                quarter_barrier(target, qid);
                layer12<HH>(g_h1 + mb*HH, W2g, As12, Bs12, g_h2, b2r,
                            tid, lane, wm, wn, g8, t4, mb, nb);

                __syncthreads();
                l3_prefB(W3g, Bs3, tid);
                quarter_barrier(target, qid);
                const int out_t = (s == 3 && sub == 2) ? t : -1;
                layer3(g_h2 + mb3*HH, W3g, As3, Bs3, Red, b3r,
                       yreg, ksreg, s, out_t, out,
                       tid, lane, wn3, wk, g8, t4, mb3, nb3);
            }
        }
    }
}

// ---------------- prep: pack weights to fragment order, init state ----------------
__global__ void prep_kernel(const float* __restrict__ x,
                            const float* __restrict__ W1,
                            const float* __restrict__ W2,
                            const float* __restrict__ W3,
                            float* __restrict__ out)
{
    int i = blockIdx.x * blockDim.x + threadIdx.x;
    if (i < 4 * 32) g_cnt[i] = 0;

    if (i < NBLK * 32768){                 // W2 pack
        int blk = i >> 15, q = i & 32767;
        int reg = q & 1, lane = (q >> 1) & 31, u = q >> 6;
        int g = u & 3, tt = u >> 2;
        int n = blk*32 + g*8 + (lane >> 2);
        int k = tt*16 + (lane & 3)*2 + reg*8;
        g_W2p[i] = packbf(__float2bfloat16(W2[k*HH + n]),
                          __float2bfloat16(W2[(k+1)*HH + n]));
    }
    if (i < NBLK * 8192){                  // W1 pack
        int blk = i >> 13, q = i & 8191;
        int reg = q & 1, lane = (q >> 1) & 31, u = q >> 6;
        int g = u & 3, tt = u >> 2;
        int n = blk*32 + g*8 + (lane >> 2);
        int k = tt*16 + (lane & 3)*2 + reg*8;
        g_W1p[i] = packbf(__float2bfloat16(W1[k*HH + n]),
                          __float2bfloat16(W1[(k+1)*HH + n]));
    }
    if (i < 32 * 16384){                   // W3 pack
        int grp = i >> 14, q = i & 16383;
        int reg = q & 1, lane = (q >> 1) & 31, u = q >> 6;
        int wn = u & 1, tt = u >> 1;
        int n = grp*16 + wn*8 + (lane >> 2);
        int k = tt*16 + (lane & 3)*2 + reg*8;
        g_W3p[i] = packbf(__float2bfloat16(W3[k*CC + n]),
                          __float2bfloat16(W3[(k+1)*CC + n]));
    }
    if (i < BB * CC){                      // state init
        int b = i >> 9, c = i & (CC - 1);
        float v = x[b * TT * CC + c];
        g_y[i] = v;
        g_a[i] = __float2bfloat16(v);
        out[b * TT * CC + c] = v;
    }
}

// ---------------- launcher: 2 graph nodes ----------------
extern "C" void kernel_launch(void* const* d_in, const int* in_sizes, int n_in,
                              void* d_out, int out_size)
{
    const float* x  = (const float*)d_in[0];
    const float* W1 = (const float*)d_in[1];
    const float* b1 = (const float*)d_in[2];
    const float* W2 = (const float*)d_in[3];
    const float* b2 = (const float*)d_in[4];
    const float* W3 = (const float*)d_in[5];
    const float* b3 = (const float*)d_in[6];
    float* out = (float*)d_out;

    (void)in_sizes; (void)n_in; (void)out_size;

    cudaFuncSetAttribute(ode_kernel, cudaFuncAttributeMaxDynamicSharedMemorySize,
                         SMEM_BYTES);

    prep_kernel<<<(NBLK * 32768 + 255) / 256, 256>>>(x, W1, W2, W3, out);
    ode_kernel<<<NCTA, 256, SMEM_BYTES>>>(b1, b2, b3, out);
}